// round 3
// baseline (speedup 1.0000x reference)
#include <cuda_runtime.h>
#include <cstddef>

// ProdLayer forward: element_mars[nids] = node_mars[cids].sum(axis=1)
//   d_in[0] node_mars     float32  [N_SRC, 128]
//   d_in[1] element_mars  float32  [N_PROD+1, 128]
//   d_in[2] nids          int32    [N_PROD]
//   d_in[3] cids          int32    [N_PROD, 4]
// Output: float32 [N_PROD+1, 128]
//
// R3: column-tiled multi-pass. 8 sequential launches, each covering a
// 16-column slice of all products. Per-pass gather footprint =
// N_SRC * 16 * 4B = 64 MB < 126 MB L2, so row re-references hit L2 instead
// of missing at the ~25% capacity ratio. Compulsory DRAM reads only.
//
// Warp layout per pass: 8 products x 16 cols per warp.
//   sub = lane>>2  -> product within warp
//   q   = lane&3   -> float4 within the 16-col slice
// cids int4 broadcasts within each 4-lane quad; output stores coalesce
// (64B per product, products contiguous). Output uses __stcs so streaming
// writes don't evict the resident slice.

static constexpr int B_F4    = 32;  // 128 floats / 4 per row
static constexpr int N_PASS  = 8;
static constexpr int F4_PER_PASS = B_F4 / N_PASS;  // 4 float4 = 16 cols

__global__ void __launch_bounds__(256) prodlayer_pass_kernel(
    const float4* __restrict__ node_mars,
    const float4* __restrict__ element_mars,
    const int*    __restrict__ nids,
    const int4*   __restrict__ cids,
    float4*       __restrict__ out,
    int n_prod,
    int pass)
{
    const int gwarp = (int)((blockIdx.x * (unsigned)blockDim.x + threadIdx.x) >> 5);
    const int lane  = threadIdx.x & 31;
    const int sub   = lane >> 2;          // product within warp (0..7)
    const int q     = lane & 3;           // float4 within slice (0..3)

    const long prod = (long)gwarp * 8 + sub;
    const int  f4   = pass * F4_PER_PASS + q;   // float4 column index in row

    if (prod < n_prod) {
        const int4 c = __ldg(&cids[prod]);      // broadcast within quad

        const float4 a = __ldg(&node_mars[(size_t)c.x * B_F4 + f4]);
        const float4 b = __ldg(&node_mars[(size_t)c.y * B_F4 + f4]);
        const float4 d = __ldg(&node_mars[(size_t)c.z * B_F4 + f4]);
        const float4 e = __ldg(&node_mars[(size_t)c.w * B_F4 + f4]);

        float4 s;
        s.x = (a.x + b.x) + (d.x + e.x);
        s.y = (a.y + b.y) + (d.y + e.y);
        s.z = (a.z + b.z) + (d.z + e.z);
        s.w = (a.w + b.w) + (d.w + e.w);

        const int o = __ldg(&nids[prod]);
        __stcs(&out[(size_t)o * B_F4 + f4], s);
    } else if (prod == n_prod) {
        // Reserved row 0: copy this pass's slice of element_mars row 0
        // (d_out is poisoned, so row 0 must be written explicitly).
        __stcs(&out[f4], __ldg(&element_mars[f4]));
    }
}

extern "C" void kernel_launch(void* const* d_in, const int* in_sizes, int n_in,
                              void* d_out, int out_size)
{
    const float4* node_mars    = (const float4*)d_in[0];
    const float4* element_mars = (const float4*)d_in[1];
    const int*    nids         = (const int*)d_in[2];
    const int4*   cids         = (const int4*)d_in[3];
    float4*       out          = (float4*)d_out;

    const int n_prod  = in_sizes[2];                  // 500000
    const int n_items = n_prod + 1;                   // +1 for reserved row 0
    const int n_warps = (n_items + 7) / 8;            // 8 products per warp
    const int threads = 256;                          // 8 warps per block
    const int blocks  = (n_warps + 7) / 8;

    for (int pass = 0; pass < N_PASS; ++pass) {
        prodlayer_pass_kernel<<<blocks, threads>>>(node_mars, element_mars,
                                                   nids, cids, out,
                                                   n_prod, pass);
    }
}

// round 5
// speedup vs baseline: 1.6795x; 1.6795x over previous
#include <cuda_runtime.h>
#include <cstddef>
#include <cstdint>

// ProdLayer forward: element_mars[nids] = node_mars[cids].sum(axis=1)
//   d_in[0] node_mars     float32  [N_SRC, 128]
//   d_in[1] element_mars  float32  [N_PROD+1, 128]
//   d_in[2] nids          int32    [N_PROD]
//   d_in[3] cids          int32    [N_PROD, 4]
// Output: float32 [N_PROD+1, 128]
//
// R5 (= R4 fixed): gather loads use createpolicy.fractional.L2::evict_last
// + ld.global.nc.L2::cache_hint (the v4.f32-legal form on sm_103; bare
// .L2::evict_last requires 256-bit loads). Streaming traffic (__stcs
// stores, __ldcs index reads) evicts itself instead of gather rows.
// 2 products per warp -> 8 front-batched LDG.128 per lane for deep MLP.

static constexpr int B_F4 = 32;  // 128 floats / 4 per row

__device__ __forceinline__ uint64_t make_evict_last_policy() {
    uint64_t pol;
    asm("createpolicy.fractional.L2::evict_last.b64 %0, 1.0;" : "=l"(pol));
    return pol;
}

__device__ __forceinline__ float4 ldg_el(const float4* p, uint64_t pol) {
    float4 v;
    asm volatile("ld.global.nc.L2::cache_hint.v4.f32 {%0,%1,%2,%3}, [%4], %5;"
                 : "=f"(v.x), "=f"(v.y), "=f"(v.z), "=f"(v.w)
                 : "l"(p), "l"(pol));
    return v;
}

__global__ void __launch_bounds__(256) prodlayer_kernel(
    const float4* __restrict__ node_mars,
    const float4* __restrict__ element_mars,
    const int*    __restrict__ nids,
    const int4*   __restrict__ cids,
    float4*       __restrict__ out,
    int n_prod)
{
    const int gwarp = (int)((blockIdx.x * (unsigned)blockDim.x + threadIdx.x) >> 5);
    const int lane  = threadIdx.x & 31;
    const uint64_t pol = make_evict_last_policy();

    const int p0 = gwarp * 2;
    const int p1 = p0 + 1;

    // Fast path: both products valid (all but the last warp).
    if (p1 < n_prod) {
        const int4 c0 = __ldcs(&cids[p0]);
        const int4 c1 = __ldcs(&cids[p1]);

        // 8 independent gathers, front-batched for MLP.
        const float4 a0 = ldg_el(&node_mars[(size_t)c0.x * B_F4 + lane], pol);
        const float4 b0 = ldg_el(&node_mars[(size_t)c0.y * B_F4 + lane], pol);
        const float4 d0 = ldg_el(&node_mars[(size_t)c0.z * B_F4 + lane], pol);
        const float4 e0 = ldg_el(&node_mars[(size_t)c0.w * B_F4 + lane], pol);
        const float4 a1 = ldg_el(&node_mars[(size_t)c1.x * B_F4 + lane], pol);
        const float4 b1 = ldg_el(&node_mars[(size_t)c1.y * B_F4 + lane], pol);
        const float4 d1 = ldg_el(&node_mars[(size_t)c1.z * B_F4 + lane], pol);
        const float4 e1 = ldg_el(&node_mars[(size_t)c1.w * B_F4 + lane], pol);

        float4 s0, s1;
        s0.x = (a0.x + b0.x) + (d0.x + e0.x);
        s0.y = (a0.y + b0.y) + (d0.y + e0.y);
        s0.z = (a0.z + b0.z) + (d0.z + e0.z);
        s0.w = (a0.w + b0.w) + (d0.w + e0.w);
        s1.x = (a1.x + b1.x) + (d1.x + e1.x);
        s1.y = (a1.y + b1.y) + (d1.y + e1.y);
        s1.z = (a1.z + b1.z) + (d1.z + e1.z);
        s1.w = (a1.w + b1.w) + (d1.w + e1.w);

        const int o0 = __ldcs(&nids[p0]);
        const int o1 = __ldcs(&nids[p1]);
        __stcs(&out[(size_t)o0 * B_F4 + lane], s0);
        __stcs(&out[(size_t)o1 * B_F4 + lane], s1);
        return;
    }

    // Tail: remaining items one by one; item index n_prod is the reserved
    // row 0 copy (d_out poisoned -> row 0 must be written explicitly).
    #pragma unroll
    for (int t = 0; t < 2; ++t) {
        const int p = p0 + t;
        if (p < n_prod) {
            const int4 c = __ldcs(&cids[p]);
            const float4 a = ldg_el(&node_mars[(size_t)c.x * B_F4 + lane], pol);
            const float4 b = ldg_el(&node_mars[(size_t)c.y * B_F4 + lane], pol);
            const float4 d = ldg_el(&node_mars[(size_t)c.z * B_F4 + lane], pol);
            const float4 e = ldg_el(&node_mars[(size_t)c.w * B_F4 + lane], pol);
            float4 s;
            s.x = (a.x + b.x) + (d.x + e.x);
            s.y = (a.y + b.y) + (d.y + e.y);
            s.z = (a.z + b.z) + (d.z + e.z);
            s.w = (a.w + b.w) + (d.w + e.w);
            const int o = __ldcs(&nids[p]);
            __stcs(&out[(size_t)o * B_F4 + lane], s);
        } else if (p == n_prod) {
            __stcs(&out[lane], __ldg(&element_mars[lane]));
        }
    }
}

extern "C" void kernel_launch(void* const* d_in, const int* in_sizes, int n_in,
                              void* d_out, int out_size)
{
    const float4* node_mars    = (const float4*)d_in[0];
    const float4* element_mars = (const float4*)d_in[1];
    const int*    nids         = (const int*)d_in[2];
    const int4*   cids         = (const int4*)d_in[3];
    float4*       out          = (float4*)d_out;

    const int n_prod  = in_sizes[2];                 // 500000
    const int n_items = n_prod + 1;                  // +1 for reserved row 0
    const int n_warps = (n_items + 1) / 2;           // 2 items per warp
    const int threads = 256;                         // 8 warps per block
    const int blocks  = (n_warps + 7) / 8;

    prodlayer_kernel<<<blocks, threads>>>(node_mars, element_mars, nids, cids,
                                          out, n_prod);
}

// round 6
// speedup vs baseline: 1.7134x; 1.0202x over previous
#include <cuda_runtime.h>
#include <cstddef>

// ProdLayer forward: element_mars[nids] = node_mars[cids].sum(axis=1)
//   d_in[0] node_mars     float32  [N_SRC, 128]
//   d_in[1] element_mars  float32  [N_PROD+1, 128]
//   d_in[2] nids          int32    [N_PROD]
//   d_in[3] cids          int32    [N_PROD, 4]
// Output: float32 [N_PROD+1, 128]
//
// R6: R2's winning cache policy (plain __ldg gathers -- L2 hit rate is
// already at the 126MB/512MB capacity ratio, policies can't beat it;
// __ldcs index reads and __stcs output stores keep streaming traffic from
// evicting gather lines) combined with 2 products per warp so each lane
// front-batches 8 independent LDG.128 (deeper DRAM request pipeline),
// without R5's createpolicy register overhead.

static constexpr int B_F4 = 32;  // 128 floats / 4 per row

__global__ void __launch_bounds__(256) prodlayer_kernel(
    const float4* __restrict__ node_mars,
    const float4* __restrict__ element_mars,
    const int*    __restrict__ nids,
    const int4*   __restrict__ cids,
    float4*       __restrict__ out,
    int n_prod)
{
    const int gwarp = (int)((blockIdx.x * (unsigned)blockDim.x + threadIdx.x) >> 5);
    const int lane  = threadIdx.x & 31;

    const int p0 = gwarp * 2;
    const int p1 = p0 + 1;

    if (p1 < n_prod) {
        const int4 c0 = __ldcs(&cids[p0]);
        const int4 c1 = __ldcs(&cids[p1]);

        // 8 independent gathers front-batched for MLP.
        const float4 a0 = __ldg(&node_mars[(size_t)c0.x * B_F4 + lane]);
        const float4 b0 = __ldg(&node_mars[(size_t)c0.y * B_F4 + lane]);
        const float4 d0 = __ldg(&node_mars[(size_t)c0.z * B_F4 + lane]);
        const float4 e0 = __ldg(&node_mars[(size_t)c0.w * B_F4 + lane]);
        const float4 a1 = __ldg(&node_mars[(size_t)c1.x * B_F4 + lane]);
        const float4 b1 = __ldg(&node_mars[(size_t)c1.y * B_F4 + lane]);
        const float4 d1 = __ldg(&node_mars[(size_t)c1.z * B_F4 + lane]);
        const float4 e1 = __ldg(&node_mars[(size_t)c1.w * B_F4 + lane]);

        float4 s0, s1;
        s0.x = (a0.x + b0.x) + (d0.x + e0.x);
        s0.y = (a0.y + b0.y) + (d0.y + e0.y);
        s0.z = (a0.z + b0.z) + (d0.z + e0.z);
        s0.w = (a0.w + b0.w) + (d0.w + e0.w);
        s1.x = (a1.x + b1.x) + (d1.x + e1.x);
        s1.y = (a1.y + b1.y) + (d1.y + e1.y);
        s1.z = (a1.z + b1.z) + (d1.z + e1.z);
        s1.w = (a1.w + b1.w) + (d1.w + e1.w);

        const int o0 = __ldcs(&nids[p0]);
        const int o1 = __ldcs(&nids[p1]);
        __stcs(&out[(size_t)o0 * B_F4 + lane], s0);
        __stcs(&out[(size_t)o1 * B_F4 + lane], s1);
        return;
    }

    // Tail: remaining items one by one; item index n_prod is the reserved
    // row 0 copy (d_out is poisoned -> row 0 must be written explicitly).
    #pragma unroll
    for (int t = 0; t < 2; ++t) {
        const int p = p0 + t;
        if (p < n_prod) {
            const int4 c = __ldcs(&cids[p]);
            const float4 a = __ldg(&node_mars[(size_t)c.x * B_F4 + lane]);
            const float4 b = __ldg(&node_mars[(size_t)c.y * B_F4 + lane]);
            const float4 d = __ldg(&node_mars[(size_t)c.z * B_F4 + lane]);
            const float4 e = __ldg(&node_mars[(size_t)c.w * B_F4 + lane]);
            float4 s;
            s.x = (a.x + b.x) + (d.x + e.x);
            s.y = (a.y + b.y) + (d.y + e.y);
            s.z = (a.z + b.z) + (d.z + e.z);
            s.w = (a.w + b.w) + (d.w + e.w);
            const int o = __ldcs(&nids[p]);
            __stcs(&out[(size_t)o * B_F4 + lane], s);
        } else if (p == n_prod) {
            __stcs(&out[lane], __ldg(&element_mars[lane]));
        }
    }
}

extern "C" void kernel_launch(void* const* d_in, const int* in_sizes, int n_in,
                              void* d_out, int out_size)
{
    const float4* node_mars    = (const float4*)d_in[0];
    const float4* element_mars = (const float4*)d_in[1];
    const int*    nids         = (const int*)d_in[2];
    const int4*   cids         = (const int4*)d_in[3];
    float4*       out          = (float4*)d_out;

    const int n_prod  = in_sizes[2];                 // 500000
    const int n_items = n_prod + 1;                  // +1 for reserved row 0
    const int n_warps = (n_items + 1) / 2;           // 2 items per warp
    const int threads = 256;                         // 8 warps per block
    const int blocks  = (n_warps + 7) / 8;

    prodlayer_kernel<<<blocks, threads>>>(node_mars, element_mars, nids, cids,
                                          out, n_prod);
}